// round 14
// baseline (speedup 1.0000x reference)
#include <cuda_runtime.h>
#include <cuda_bf16.h>

#define B_  4
#define T_  2048
#define C_  1024
#define NH_ 16
#define D_  64
#define BT_ (B_ * T_)      // 8192
#define C3_ (3 * C_)       // 3072

// ---- persistent bf16 hi/lo operand storage (no allocation allowed) ----
__device__ __nv_bfloat16 g_xH[(size_t)BT_ * C_],  g_xL[(size_t)BT_ * C_];
__device__ __nv_bfloat16 g_WaH[(size_t)C_ * C3_], g_WaL[(size_t)C_ * C3_];
__device__ __nv_bfloat16 g_WpH[(size_t)C_ * C_],  g_WpL[(size_t)C_ * C_];
__device__ __nv_bfloat16 g_qkvH[(size_t)BT_ * C3_], g_qkvL[(size_t)BT_ * C3_];
__device__ __nv_bfloat16 g_yH[(size_t)BT_ * C_],  g_yL[(size_t)BT_ * C_];

// ---------------- bf16 helpers ----------------
__device__ __forceinline__ void split4bf(float4 v, uint2 &h, uint2 &l) {
    float e[4] = { v.x, v.y, v.z, v.w };
    unsigned hs[4], ls[4];
    #pragma unroll
    for (int i = 0; i < 4; i++) {
        __nv_bfloat16 bh = __float2bfloat16(e[i]);
        hs[i] = __bfloat16_as_ushort(bh);
        ls[i] = __bfloat16_as_ushort(__float2bfloat16(e[i] - __bfloat162float(bh)));
    }
    h.x = hs[0] | (hs[1] << 16);  h.y = hs[2] | (hs[3] << 16);
    l.x = ls[0] | (ls[1] << 16);  l.y = ls[2] | (ls[3] << 16);
}
__device__ __forceinline__ unsigned pk2bf(float a, float b) {
    return __bfloat16_as_ushort(__float2bfloat16(a)) |
           ((unsigned)__bfloat16_as_ushort(__float2bfloat16(b)) << 16);
}
__device__ __forceinline__ float bflo(float x) {
    return x - __bfloat162float(__float2bfloat16(x));
}
__device__ __forceinline__ void mmabf(float c[4], const unsigned a[4], const unsigned b[2]) {
    asm("mma.sync.aligned.m16n8k16.row.col.f32.bf16.bf16.f32 "
        "{%0,%1,%2,%3}, {%4,%5,%6,%7}, {%8,%9}, {%0,%1,%2,%3};"
        : "+f"(c[0]), "+f"(c[1]), "+f"(c[2]), "+f"(c[3])
        : "r"(a[0]), "r"(a[1]), "r"(a[2]), "r"(a[3]), "r"(b[0]), "r"(b[1]));
}
__device__ __forceinline__ void ldsm4(unsigned r[4], unsigned a) {
    asm volatile("ldmatrix.sync.aligned.m8n8.x4.shared.b16 {%0,%1,%2,%3}, [%4];"
        : "=r"(r[0]), "=r"(r[1]), "=r"(r[2]), "=r"(r[3]) : "r"(a));
}
__device__ __forceinline__ void ldsm4t(unsigned r[4], unsigned a) {
    asm volatile("ldmatrix.sync.aligned.m8n8.x4.trans.shared.b16 {%0,%1,%2,%3}, [%4];"
        : "=r"(r[0]), "=r"(r[1]), "=r"(r[2]), "=r"(r[3]) : "r"(a));
}
__device__ __forceinline__ unsigned sptr(const void* p) {
    return (unsigned)__cvta_generic_to_shared(p);
}
__device__ __forceinline__ void cp16(unsigned s, const void* g) {
    asm volatile("cp.async.ca.shared.global [%0], [%1], 16;" :: "r"(s), "l"(g));
}
__device__ __forceinline__ void cpcommit() { asm volatile("cp.async.commit_group;"); }
__device__ __forceinline__ void cpwait0()  { asm volatile("cp.async.wait_group 0;" ::: "memory"); }
__device__ __forceinline__ void cpwait1()  { asm volatile("cp.async.wait_group 1;" ::: "memory"); }
__device__ __forceinline__ void cpwait2()  { asm volatile("cp.async.wait_group 2;" ::: "memory"); }

// ---------------------------------------------------------------------------
// Prepass: split float -> bf16 hi/lo
// ---------------------------------------------------------------------------
__global__ void split_kernel(const float* __restrict__ src,
                             __nv_bfloat16* __restrict__ h,
                             __nv_bfloat16* __restrict__ l, int n4)
{
    int i = blockIdx.x * blockDim.x + threadIdx.x;
    if (i < n4) {
        float4 v = ((const float4*)src)[i];
        uint2 hh, ll; split4bf(v, hh, ll);
        ((uint2*)h)[i] = hh; ((uint2*)l)[i] = ll;
    }
}

// ---------------------------------------------------------------------------
// bf16x3 GEMM: cp.async double buffer, one barrier per k-tile.
// ---------------------------------------------------------------------------
template<int MODE>
__global__ __launch_bounds__(256) void gemm_bf16(
    const __nv_bfloat16* __restrict__ AHg, const __nv_bfloat16* __restrict__ ALg,
    const __nv_bfloat16* __restrict__ WHg, const __nv_bfloat16* __restrict__ WLg,
    const float* __restrict__ bias, const float* __restrict__ bQ,
    const float* __restrict__ bK, float* __restrict__ CoutF,
    __nv_bfloat16* __restrict__ CoutH, __nv_bfloat16* __restrict__ CoutL,
    int M, int N, int K)
{
    extern __shared__ __align__(16) unsigned short smg[];

    const int tid = threadIdx.x, lane = tid & 31, warp = tid >> 5;
    const int g = lane >> 2, c = lane & 3;
    const int wm = warp >> 2, wn = warp & 3;
    const int crow = blockIdx.y * 128, ccol = blockIdx.x * 128;

    float acc[4][4][4];
    #pragma unroll
    for (int i = 0; i < 4; i++)
        #pragma unroll
        for (int j = 0; j < 4; j++)
            #pragma unroll
            for (int f = 0; f < 4; f++) acc[i][j][f] = 0.f;

    int ar[2], ac[2], br[2], bc[2];
    #pragma unroll
    for (int q = 0; q < 2; q++) {
        int cid = tid + 256 * q;
        ar[q] = cid >> 2;  ac[q] = (cid & 3) * 8;
        br[q] = cid >> 4;  bc[q] = (cid & 15) * 8;
    }
    const unsigned smbase = sptr(smg);

    const int rowA = wm * 64 + (lane & 7) + ((lane >> 3) & 1) * 8;
    const unsigned aAHb = smbase + (rowA * 40 + ((lane >> 4) & 1) * 8) * 2;
    const int rowB = (lane & 7) + ((lane >> 3) & 1) * 8;
    const int colB = wn * 32 + ((lane >> 4) & 1) * 8;
    const unsigned aBHb = smbase + (20480 + rowB * 136 + colB) * 2;

    const int nk = K >> 5;

    auto load_tile = [&](int kt, int st) {
        #pragma unroll
        for (int q = 0; q < 2; q++) {
            unsigned sa = smbase + (st * 5120 + ar[q] * 40 + ac[q]) * 2;
            cp16(sa, &AHg[(size_t)(crow + ar[q]) * K + kt * 32 + ac[q]]);
            cp16(sa + 20480, &ALg[(size_t)(crow + ar[q]) * K + kt * 32 + ac[q]]);
            unsigned sb = smbase + (20480 + st * 4352 + br[q] * 136 + bc[q]) * 2;
            cp16(sb, &WHg[(size_t)(kt * 32 + br[q]) * N + ccol + bc[q]]);
            cp16(sb + 17408, &WLg[(size_t)(kt * 32 + br[q]) * N + ccol + bc[q]]);
        }
        cpcommit();
    };

    load_tile(0, 0);

    for (int kt = 0; kt < nk; kt++) {
        const int st = kt & 1;
        cpwait0();
        __syncthreads();
        if (kt + 1 < nk) load_tile(kt + 1, st ^ 1);

        const unsigned aA = aAHb + st * 10240;
        const unsigned aB = aBHb + st * 8704;
        #pragma unroll
        for (int ks = 0; ks < 2; ks++) {
            unsigned bh[4][2], bl[4][2];
            #pragma unroll
            for (int ntp = 0; ntp < 2; ntp++) {
                unsigned off = (ks * 16 * 136 + ntp * 16) * 2;
                unsigned t[4];
                ldsm4t(t, aB + off);
                bh[2 * ntp][0] = t[0]; bh[2 * ntp][1] = t[1];
                bh[2 * ntp + 1][0] = t[2]; bh[2 * ntp + 1][1] = t[3];
                ldsm4t(t, aB + 17408 + off);
                bl[2 * ntp][0] = t[0]; bl[2 * ntp][1] = t[1];
                bl[2 * ntp + 1][0] = t[2]; bl[2 * ntp + 1][1] = t[3];
            }
            #pragma unroll
            for (int mt = 0; mt < 4; mt++) {
                unsigned off = (mt * 16 * 40 + ks * 16) * 2;
                unsigned ah[4], al[4];
                ldsm4(ah, aA + off);
                ldsm4(al, aA + 20480 + off);
                #pragma unroll
                for (int nt = 0; nt < 4; nt++) {
                    mmabf(acc[mt][nt], ah, bh[nt]);
                    mmabf(acc[mt][nt], ah, bl[nt]);
                    mmabf(acc[mt][nt], al, bh[nt]);
                }
            }
        }
        // no trailing __syncthreads: next iteration's top barrier separates
        // compute(kt) from the load that overwrites stage st.
    }

    #pragma unroll
    for (int mt = 0; mt < 4; mt++)
    #pragma unroll
    for (int hh = 0; hh < 2; hh++) {
        int row = crow + wm * 64 + mt * 16 + g + 8 * hh;
        #pragma unroll
        for (int nt = 0; nt < 4; nt++) {
            int n0 = ccol + wn * 32 + nt * 8 + 2 * c;
            float v0 = acc[mt][nt][2 * hh]     + bias[n0];
            float v1 = acc[mt][nt][2 * hh + 1] + bias[n0 + 1];
            if (MODE == 0) {
                if (n0 < C_)          { v0 = (v0 + bQ[n0]) * 0.125f; v1 = (v1 + bQ[n0 + 1]) * 0.125f; }
                else if (n0 < 2 * C_) { v0 += bK[n0 - C_];           v1 += bK[n0 + 1 - C_]; }
                size_t o = (size_t)row * N + n0;
                *(unsigned*)&CoutH[o] = pk2bf(v0, v1);
                *(unsigned*)&CoutL[o] = pk2bf(bflo(v0), bflo(v1));
            } else {
                *(float2*)&CoutF[(size_t)row * N + n0] = make_float2(v0, v1);
            }
        }
    }
}

// ---------------------------------------------------------------------------
// Flash attention: bf16x3, Bk=32, 3-stage cp.async ring, Q hi-frags in regs.
// CTA = 128 q-rows x (h, b); 8 warps; 2 CTAs/SM target (92160 B smem).
// ---------------------------------------------------------------------------
#define ASMEM_BYTES 92160

__global__ __launch_bounds__(256, 2) void attn_bf16()
{
    extern __shared__ __align__(16) unsigned short smn[];
    const unsigned smbase = sptr(smn);

    const int tid = threadIdx.x, lane = tid & 31, w = tid >> 5;
    const int g = lane >> 2, c = lane & 3;
    const int qt = blockIdx.x, h = blockIdx.y, b = blockIdx.z;
    const int q0 = qt * 128;
    const size_t rb = (size_t)b * T_ * C3_ + (size_t)h * D_;

    const int nkt = 4 * qt + 4;   // 32-col tiles

    auto load_kv = [&](int kt, int st) {
        int kc = tid >> 3, d0 = (tid & 7) * 8;
        size_t go = rb + (size_t)(kt * 32 + kc) * C3_ + d0;
        unsigned sb = smbase + 36864 + st * 18432 + kc * 144 + d0 * 2;
        cp16(sb,          &g_qkvH[go + C_]);
        cp16(sb + 4608,   &g_qkvL[go + C_]);
        cp16(sb + 9216,   &g_qkvH[go + 2 * C_]);
        cp16(sb + 13824,  &g_qkvL[go + 2 * C_]);
        cpcommit();
    };

    // Prologue: Q (group 0), KV0 (group 1), KV1 (group 2)
    #pragma unroll
    for (int r = 0; r < 4; r++) {
        int idx = tid + 256 * r;
        int qq = idx >> 3, d0 = (idx & 7) * 8;
        size_t gi = rb + (size_t)(q0 + qq) * C3_ + d0;
        unsigned sb = smbase + qq * 144 + d0 * 2;
        cp16(sb, &g_qkvH[gi]);
        cp16(sb + 18432, &g_qkvL[gi]);
    }
    cpcommit();
    load_kv(0, 0);
    load_kv(1, 1);

    const int rQ = w * 16 + (lane & 7) + ((lane >> 3) & 1) * 8;
    const unsigned aQH = smbase + rQ * 144 + ((lane >> 4) & 1) * 16;
    const unsigned aQL = aQH + 18432;
    const int rK = (lane & 7) + ((lane >> 4) & 1) * 8;
    const unsigned kOff = rK * 144 + ((lane >> 3) & 1) * 16;
    const int rV = (lane & 7) + ((lane >> 3) & 1) * 8;
    const unsigned vOff = 9216 + rV * 144 + ((lane >> 4) & 1) * 16;

    cpwait2();            // Q (group 0) complete
    __syncthreads();
    unsigned qh[4][4];
    #pragma unroll
    for (int ks = 0; ks < 4; ks++) ldsm4(qh[ks], aQH + ks * 32);

    float m0 = -1e30f, m1 = -1e30f, l0 = 0.f, l1 = 0.f;
    float o[8][4];
    #pragma unroll
    for (int nt = 0; nt < 8; nt++)
        #pragma unroll
        for (int f = 0; f < 4; f++) o[nt][f] = 0.f;

    const int row0 = q0 + w * 16 + g, row1 = row0 + 8;

    for (int kt = 0; kt < nkt; kt++) {
        const int st = kt % 3;
        cpwait1();
        __syncthreads();
        if (kt + 2 < nkt) load_kv(kt + 2, (kt + 2) % 3);

        const unsigned sbkv = smbase + 36864 + st * 18432;
        const unsigned aKH = sbkv + kOff,  aKL = aKH + 4608;
        const unsigned aVH = sbkv + vOff,  aVL = aVH + 4608;

        // ---- S = Q K^T (3-term), 32 kv cols ----
        float s[4][4];
        #pragma unroll
        for (int nt = 0; nt < 4; nt++)
            #pragma unroll
            for (int f = 0; f < 4; f++) s[nt][f] = 0.f;

        #pragma unroll
        for (int ks = 0; ks < 4; ks++) {
            unsigned ql[4];
            ldsm4(ql, aQL + ks * 32);
            unsigned bh[4][2], bl[4][2];
            #pragma unroll
            for (int ntp = 0; ntp < 2; ntp++) {
                unsigned off = (ntp * 16 * 72 + ks * 16) * 2;
                unsigned t[4];
                ldsm4(t, aKH + off);
                bh[2 * ntp][0] = t[0]; bh[2 * ntp][1] = t[1];
                bh[2 * ntp + 1][0] = t[2]; bh[2 * ntp + 1][1] = t[3];
                ldsm4(t, aKL + off);
                bl[2 * ntp][0] = t[0]; bl[2 * ntp][1] = t[1];
                bl[2 * ntp + 1][0] = t[2]; bl[2 * ntp + 1][1] = t[3];
            }
            #pragma unroll
            for (int nt = 0; nt < 4; nt++) {
                mmabf(s[nt], qh[ks], bh[nt]);
                mmabf(s[nt], qh[ks], bl[nt]);
                mmabf(s[nt], ql, bh[nt]);
            }
        }

        if (kt >= 4 * qt) {   // diagonal band tiles only
            #pragma unroll
            for (int nt = 0; nt < 4; nt++) {
                int col = kt * 32 + nt * 8 + 2 * c;
                if (col     > row0) s[nt][0] = -1e30f;
                if (col + 1 > row0) s[nt][1] = -1e30f;
                if (col     > row1) s[nt][2] = -1e30f;
                if (col + 1 > row1) s[nt][3] = -1e30f;
            }
        }

        // ---- online softmax ----
        float mx0 = -1e30f, mx1 = -1e30f;
        #pragma unroll
        for (int nt = 0; nt < 4; nt++) {
            mx0 = fmaxf(mx0, fmaxf(s[nt][0], s[nt][1]));
            mx1 = fmaxf(mx1, fmaxf(s[nt][2], s[nt][3]));
        }
        mx0 = fmaxf(mx0, __shfl_xor_sync(0xffffffffu, mx0, 1));
        mx0 = fmaxf(mx0, __shfl_xor_sync(0xffffffffu, mx0, 2));
        mx1 = fmaxf(mx1, __shfl_xor_sync(0xffffffffu, mx1, 1));
        mx1 = fmaxf(mx1, __shfl_xor_sync(0xffffffffu, mx1, 2));
        float mn0 = fmaxf(m0, mx0), mn1 = fmaxf(m1, mx1);
        float a0 = __expf(m0 - mn0), a1 = __expf(m1 - mn1);
        float sum0 = 0.f, sum1 = 0.f;
        #pragma unroll
        for (int nt = 0; nt < 4; nt++) {
            s[nt][0] = __expf(s[nt][0] - mn0);
            s[nt][1] = __expf(s[nt][1] - mn0);
            s[nt][2] = __expf(s[nt][2] - mn1);
            s[nt][3] = __expf(s[nt][3] - mn1);
            sum0 += s[nt][0] + s[nt][1];
            sum1 += s[nt][2] + s[nt][3];
        }
        sum0 += __shfl_xor_sync(0xffffffffu, sum0, 1);
        sum0 += __shfl_xor_sync(0xffffffffu, sum0, 2);
        sum1 += __shfl_xor_sync(0xffffffffu, sum1, 1);
        sum1 += __shfl_xor_sync(0xffffffffu, sum1, 2);
        l0 = l0 * a0 + sum0;  m0 = mn0;
        l1 = l1 * a1 + sum1;  m1 = mn1;
        #pragma unroll
        for (int nt = 0; nt < 8; nt++) {
            o[nt][0] *= a0; o[nt][1] *= a0;
            o[nt][2] *= a1; o[nt][3] *= a1;
        }

        // ---- P in registers (hi + lo) ----
        unsigned ph[4][2], pl[4][2];
        #pragma unroll
        for (int nt = 0; nt < 4; nt++) {
            ph[nt][0] = pk2bf(s[nt][0], s[nt][1]);
            ph[nt][1] = pk2bf(s[nt][2], s[nt][3]);
            pl[nt][0] = pk2bf(bflo(s[nt][0]), bflo(s[nt][1]));
            pl[nt][1] = pk2bf(bflo(s[nt][2]), bflo(s[nt][3]));
        }

        // ---- O += P V (3-term), kdim 32 ----
        #pragma unroll
        for (int ks = 0; ks < 2; ks++) {
            unsigned pah[4] = { ph[2 * ks][0], ph[2 * ks][1], ph[2 * ks + 1][0], ph[2 * ks + 1][1] };
            unsigned pal[4] = { pl[2 * ks][0], pl[2 * ks][1], pl[2 * ks + 1][0], pl[2 * ks + 1][1] };
            unsigned bh[8][2], bl[8][2];
            #pragma unroll
            for (int ntp = 0; ntp < 4; ntp++) {
                unsigned off = (ks * 16 * 72 + ntp * 16) * 2;
                unsigned t[4];
                ldsm4t(t, aVH + off);
                bh[2 * ntp][0] = t[0]; bh[2 * ntp][1] = t[1];
                bh[2 * ntp + 1][0] = t[2]; bh[2 * ntp + 1][1] = t[3];
                ldsm4t(t, aVL + off);
                bl[2 * ntp][0] = t[0]; bl[2 * ntp][1] = t[1];
                bl[2 * ntp + 1][0] = t[2]; bl[2 * ntp + 1][1] = t[3];
            }
            #pragma unroll
            for (int nt = 0; nt < 8; nt++) {
                mmabf(o[nt], pah, bh[nt]);
                mmabf(o[nt], pah, bl[nt]);
                mmabf(o[nt], pal, bh[nt]);
            }
        }
    }

    // normalize + write yH/yL
    float i0 = 1.f / l0, i1 = 1.f / l1;
    #pragma unroll
    for (int nt = 0; nt < 8; nt++) {
        int col = h * D_ + nt * 8 + 2 * c;
        float y00 = o[nt][0] * i0, y01 = o[nt][1] * i0;
        float y10 = o[nt][2] * i1, y11 = o[nt][3] * i1;
        size_t o0 = (size_t)(b * T_ + row0) * C_ + col;
        size_t o1 = (size_t)(b * T_ + row1) * C_ + col;
        *(unsigned*)&g_yH[o0] = pk2bf(y00, y01);
        *(unsigned*)&g_yL[o0] = pk2bf(bflo(y00), bflo(y01));
        *(unsigned*)&g_yH[o1] = pk2bf(y10, y11);
        *(unsigned*)&g_yL[o1] = pk2bf(bflo(y10), bflo(y11));
    }
}

// ---------------------------------------------------------------------------
#define GSMEM_BYTES 75776

extern "C" void kernel_launch(void* const* d_in, const int* in_sizes, int n_in,
                              void* d_out, int out_size)
{
    const float* x      = (const float*)d_in[0];
    const float* W_attn = (const float*)d_in[1];
    const float* b_attn = (const float*)d_in[2];
    const float* bQ     = (const float*)d_in[3];
    const float* bK     = (const float*)d_in[4];
    const float* W_proj = (const float*)d_in[5];
    const float* b_proj = (const float*)d_in[6];
    float* out = (float*)d_out;

    __nv_bfloat16 *xH, *xL, *WaH, *WaL, *WpH, *WpL, *qkvH, *qkvL, *yH, *yL;
    cudaGetSymbolAddress((void**)&xH, g_xH);     cudaGetSymbolAddress((void**)&xL, g_xL);
    cudaGetSymbolAddress((void**)&WaH, g_WaH);   cudaGetSymbolAddress((void**)&WaL, g_WaL);
    cudaGetSymbolAddress((void**)&WpH, g_WpH);   cudaGetSymbolAddress((void**)&WpL, g_WpL);
    cudaGetSymbolAddress((void**)&qkvH, g_qkvH); cudaGetSymbolAddress((void**)&qkvL, g_qkvL);
    cudaGetSymbolAddress((void**)&yH, g_yH);     cudaGetSymbolAddress((void**)&yL, g_yL);

    cudaFuncSetAttribute(gemm_bf16<0>, cudaFuncAttributeMaxDynamicSharedMemorySize, GSMEM_BYTES);
    cudaFuncSetAttribute(gemm_bf16<1>, cudaFuncAttributeMaxDynamicSharedMemorySize, GSMEM_BYTES);
    cudaFuncSetAttribute(attn_bf16, cudaFuncAttributeMaxDynamicSharedMemorySize, ASMEM_BYTES);

    // prepass: split operands once
    {
        int n4x = BT_ * C_ / 4, n4a = C_ * C3_ / 4, n4p = C_ * C_ / 4;
        split_kernel<<<(n4x + 255) / 256, 256>>>(x, xH, xL, n4x);
        split_kernel<<<(n4a + 255) / 256, 256>>>(W_attn, WaH, WaL, n4a);
        split_kernel<<<(n4p + 255) / 256, 256>>>(W_proj, WpH, WpL, n4p);
    }

    // 1) qkv (bf16 hi/lo out)
    gemm_bf16<0><<<dim3(C3_ / 128, BT_ / 128), 256, GSMEM_BYTES>>>(
        xH, xL, WaH, WaL, b_attn, bQ, bK, nullptr, qkvH, qkvL, BT_, C3_, C_);

    // 2) flash attention (bf16 hi/lo out)
    attn_bf16<<<dim3(T_ / 128, NH_, B_), 256, ASMEM_BYTES>>>();

    // 3) proj (float out)
    gemm_bf16<1><<<dim3(C_ / 128, BT_ / 128), 256, GSMEM_BYTES>>>(
        yH, yL, WpH, WpL, b_proj, nullptr, nullptr, out, nullptr, nullptr, BT_, C_, C_);
}

// round 15
// speedup vs baseline: 1.5936x; 1.5936x over previous
#include <cuda_runtime.h>
#include <cuda_bf16.h>

#define B_  4
#define T_  2048
#define C_  1024
#define NH_ 16
#define D_  64
#define BT_ (B_ * T_)      // 8192
#define C3_ (3 * C_)       // 3072

// ---- persistent bf16 hi/lo operand storage (no allocation allowed) ----
__device__ __nv_bfloat16 g_xH[(size_t)BT_ * C_],  g_xL[(size_t)BT_ * C_];
__device__ __nv_bfloat16 g_WaH[(size_t)C_ * C3_], g_WaL[(size_t)C_ * C3_];
__device__ __nv_bfloat16 g_WpH[(size_t)C_ * C_],  g_WpL[(size_t)C_ * C_];
__device__ __nv_bfloat16 g_qkvH[(size_t)BT_ * C3_], g_qkvL[(size_t)BT_ * C3_];
__device__ __nv_bfloat16 g_yH[(size_t)BT_ * C_],  g_yL[(size_t)BT_ * C_];

// ---------------- bf16 helpers ----------------
__device__ __forceinline__ void split4bf(float4 v, uint2 &h, uint2 &l) {
    float e[4] = { v.x, v.y, v.z, v.w };
    unsigned hs[4], ls[4];
    #pragma unroll
    for (int i = 0; i < 4; i++) {
        __nv_bfloat16 bh = __float2bfloat16(e[i]);
        hs[i] = __bfloat16_as_ushort(bh);
        ls[i] = __bfloat16_as_ushort(__float2bfloat16(e[i] - __bfloat162float(bh)));
    }
    h.x = hs[0] | (hs[1] << 16);  h.y = hs[2] | (hs[3] << 16);
    l.x = ls[0] | (ls[1] << 16);  l.y = ls[2] | (ls[3] << 16);
}
__device__ __forceinline__ unsigned pk2bf(float a, float b) {
    return __bfloat16_as_ushort(__float2bfloat16(a)) |
           ((unsigned)__bfloat16_as_ushort(__float2bfloat16(b)) << 16);
}
__device__ __forceinline__ float bflo(float x) {
    return x - __bfloat162float(__float2bfloat16(x));
}
__device__ __forceinline__ void mmabf(float c[4], const unsigned a[4], const unsigned b[2]) {
    asm("mma.sync.aligned.m16n8k16.row.col.f32.bf16.bf16.f32 "
        "{%0,%1,%2,%3}, {%4,%5,%6,%7}, {%8,%9}, {%0,%1,%2,%3};"
        : "+f"(c[0]), "+f"(c[1]), "+f"(c[2]), "+f"(c[3])
        : "r"(a[0]), "r"(a[1]), "r"(a[2]), "r"(a[3]), "r"(b[0]), "r"(b[1]));
}
__device__ __forceinline__ void ldsm4(unsigned r[4], unsigned a) {
    asm volatile("ldmatrix.sync.aligned.m8n8.x4.shared.b16 {%0,%1,%2,%3}, [%4];"
        : "=r"(r[0]), "=r"(r[1]), "=r"(r[2]), "=r"(r[3]) : "r"(a));
}
__device__ __forceinline__ void ldsm4t(unsigned r[4], unsigned a) {
    asm volatile("ldmatrix.sync.aligned.m8n8.x4.trans.shared.b16 {%0,%1,%2,%3}, [%4];"
        : "=r"(r[0]), "=r"(r[1]), "=r"(r[2]), "=r"(r[3]) : "r"(a));
}
__device__ __forceinline__ unsigned sptr(const void* p) {
    return (unsigned)__cvta_generic_to_shared(p);
}
__device__ __forceinline__ void cp16(unsigned s, const void* g) {
    asm volatile("cp.async.ca.shared.global [%0], [%1], 16;" :: "r"(s), "l"(g));
}
__device__ __forceinline__ void cpcommit() { asm volatile("cp.async.commit_group;"); }
__device__ __forceinline__ void cpwait0()  { asm volatile("cp.async.wait_group 0;" ::: "memory"); }
__device__ __forceinline__ void cpwait1()  { asm volatile("cp.async.wait_group 1;" ::: "memory"); }

// ---------------------------------------------------------------------------
// Prepass: split float -> bf16 hi/lo
// ---------------------------------------------------------------------------
__global__ void split_kernel(const float* __restrict__ src,
                             __nv_bfloat16* __restrict__ h,
                             __nv_bfloat16* __restrict__ l, int n4)
{
    int i = blockIdx.x * blockDim.x + threadIdx.x;
    if (i < n4) {
        float4 v = ((const float4*)src)[i];
        uint2 hh, ll; split4bf(v, hh, ll);
        ((uint2*)h)[i] = hh; ((uint2*)l)[i] = ll;
    }
}

// ---------------------------------------------------------------------------
// bf16x3 GEMM — EXACT R8 version (trailing sync kept; regs 126, 2 CTA/SM).
// ---------------------------------------------------------------------------
template<int MODE>
__global__ __launch_bounds__(256) void gemm_bf16(
    const __nv_bfloat16* __restrict__ AHg, const __nv_bfloat16* __restrict__ ALg,
    const __nv_bfloat16* __restrict__ WHg, const __nv_bfloat16* __restrict__ WLg,
    const float* __restrict__ bias, const float* __restrict__ bQ,
    const float* __restrict__ bK, float* __restrict__ CoutF,
    __nv_bfloat16* __restrict__ CoutH, __nv_bfloat16* __restrict__ CoutL,
    int M, int N, int K)
{
    extern __shared__ __align__(16) unsigned short smg[];

    const int tid = threadIdx.x, lane = tid & 31, warp = tid >> 5;
    const int g = lane >> 2, c = lane & 3;
    const int wm = warp >> 2, wn = warp & 3;
    const int crow = blockIdx.y * 128, ccol = blockIdx.x * 128;

    float acc[4][4][4];
    #pragma unroll
    for (int i = 0; i < 4; i++)
        #pragma unroll
        for (int j = 0; j < 4; j++)
            #pragma unroll
            for (int f = 0; f < 4; f++) acc[i][j][f] = 0.f;

    int ar[2], ac[2], br[2], bc[2];
    #pragma unroll
    for (int q = 0; q < 2; q++) {
        int cid = tid + 256 * q;
        ar[q] = cid >> 2;  ac[q] = (cid & 3) * 8;
        br[q] = cid >> 4;  bc[q] = (cid & 15) * 8;
    }
    const unsigned smbase = sptr(smg);

    const int rowA = wm * 64 + (lane & 7) + ((lane >> 3) & 1) * 8;
    const unsigned aAHb = smbase + (rowA * 40 + ((lane >> 4) & 1) * 8) * 2;
    const int rowB = (lane & 7) + ((lane >> 3) & 1) * 8;
    const int colB = wn * 32 + ((lane >> 4) & 1) * 8;
    const unsigned aBHb = smbase + (20480 + rowB * 136 + colB) * 2;

    const int nk = K >> 5;

    auto load_tile = [&](int kt, int st) {
        #pragma unroll
        for (int q = 0; q < 2; q++) {
            unsigned sa = smbase + (st * 5120 + ar[q] * 40 + ac[q]) * 2;
            cp16(sa, &AHg[(size_t)(crow + ar[q]) * K + kt * 32 + ac[q]]);
            cp16(sa + 20480, &ALg[(size_t)(crow + ar[q]) * K + kt * 32 + ac[q]]);
            unsigned sb = smbase + (20480 + st * 4352 + br[q] * 136 + bc[q]) * 2;
            cp16(sb, &WHg[(size_t)(kt * 32 + br[q]) * N + ccol + bc[q]]);
            cp16(sb + 17408, &WLg[(size_t)(kt * 32 + br[q]) * N + ccol + bc[q]]);
        }
        cpcommit();
    };

    load_tile(0, 0);

    for (int kt = 0; kt < nk; kt++) {
        const int st = kt & 1;
        cpwait0();
        __syncthreads();
        if (kt + 1 < nk) load_tile(kt + 1, st ^ 1);

        const unsigned aA = aAHb + st * 10240;
        const unsigned aB = aBHb + st * 8704;
        #pragma unroll
        for (int ks = 0; ks < 2; ks++) {
            unsigned bh[4][2], bl[4][2];
            #pragma unroll
            for (int ntp = 0; ntp < 2; ntp++) {
                unsigned off = (ks * 16 * 136 + ntp * 16) * 2;
                unsigned t[4];
                ldsm4t(t, aB + off);
                bh[2 * ntp][0] = t[0]; bh[2 * ntp][1] = t[1];
                bh[2 * ntp + 1][0] = t[2]; bh[2 * ntp + 1][1] = t[3];
                ldsm4t(t, aB + 17408 + off);
                bl[2 * ntp][0] = t[0]; bl[2 * ntp][1] = t[1];
                bl[2 * ntp + 1][0] = t[2]; bl[2 * ntp + 1][1] = t[3];
            }
            #pragma unroll
            for (int mt = 0; mt < 4; mt++) {
                unsigned off = (mt * 16 * 40 + ks * 16) * 2;
                unsigned ah[4], al[4];
                ldsm4(ah, aA + off);
                ldsm4(al, aA + 20480 + off);
                #pragma unroll
                for (int nt = 0; nt < 4; nt++) {
                    mmabf(acc[mt][nt], ah, bh[nt]);
                    mmabf(acc[mt][nt], ah, bl[nt]);
                    mmabf(acc[mt][nt], al, bh[nt]);
                }
            }
        }
        __syncthreads();
    }

    #pragma unroll
    for (int mt = 0; mt < 4; mt++)
    #pragma unroll
    for (int hh = 0; hh < 2; hh++) {
        int row = crow + wm * 64 + mt * 16 + g + 8 * hh;
        #pragma unroll
        for (int nt = 0; nt < 4; nt++) {
            int n0 = ccol + wn * 32 + nt * 8 + 2 * c;
            float v0 = acc[mt][nt][2 * hh]     + bias[n0];
            float v1 = acc[mt][nt][2 * hh + 1] + bias[n0 + 1];
            if (MODE == 0) {
                if (n0 < C_)          { v0 = (v0 + bQ[n0]) * 0.125f; v1 = (v1 + bQ[n0 + 1]) * 0.125f; }
                else if (n0 < 2 * C_) { v0 += bK[n0 - C_];           v1 += bK[n0 + 1 - C_]; }
                size_t o = (size_t)row * N + n0;
                *(unsigned*)&CoutH[o] = pk2bf(v0, v1);
                *(unsigned*)&CoutL[o] = pk2bf(bflo(v0), bflo(v1));
            } else {
                *(float2*)&CoutF[(size_t)row * N + n0] = make_float2(v0, v1);
            }
        }
    }
}

// ---------------------------------------------------------------------------
// Flash attention: bf16x3, Bk=32, 3-stage cp.async ring, NO Q-hoist (regs<128).
// CTA = 128 q-rows x (h, b); 8 warps; __launch_bounds__(256,2) -> 2 CTAs/SM.
// smem bytes: QH 0 (18432) | QL 18432 | stage s at 36864 + s*18432:
//   KH +0 | KL +4608 | VH +9216 | VL +13824.   Total 92160 B.
// ---------------------------------------------------------------------------
#define ASMEM_BYTES 92160

__global__ __launch_bounds__(256, 2) void attn_bf16()
{
    extern __shared__ __align__(16) unsigned short smn[];
    const unsigned smbase = sptr(smn);

    const int tid = threadIdx.x, lane = tid & 31, w = tid >> 5;
    const int g = lane >> 2, c = lane & 3;
    const int qt = blockIdx.x, h = blockIdx.y, b = blockIdx.z;
    const int q0 = qt * 128;
    const size_t rb = (size_t)b * T_ * C3_ + (size_t)h * D_;

    const int nkt = 4 * qt + 4;   // 32-col tiles

    auto load_kv = [&](int kt, int st) {
        int kc = tid >> 3, d0 = (tid & 7) * 8;
        size_t go = rb + (size_t)(kt * 32 + kc) * C3_ + d0;
        unsigned sb = smbase + 36864 + st * 18432 + kc * 144 + d0 * 2;
        cp16(sb,          &g_qkvH[go + C_]);
        cp16(sb + 4608,   &g_qkvL[go + C_]);
        cp16(sb + 9216,   &g_qkvH[go + 2 * C_]);
        cp16(sb + 13824,  &g_qkvL[go + 2 * C_]);
        cpcommit();
    };

    // Prologue: Q (group 0), KV0 (group 1), KV1 (group 2)
    #pragma unroll
    for (int r = 0; r < 4; r++) {
        int idx = tid + 256 * r;
        int qq = idx >> 3, d0 = (idx & 7) * 8;
        size_t gi = rb + (size_t)(q0 + qq) * C3_ + d0;
        unsigned sb = smbase + qq * 144 + d0 * 2;
        cp16(sb, &g_qkvH[gi]);
        cp16(sb + 18432, &g_qkvL[gi]);
    }
    cpcommit();
    load_kv(0, 0);
    load_kv(1, 1);

    // ldmatrix lane addresses
    const int rQ = w * 16 + (lane & 7) + ((lane >> 3) & 1) * 8;
    const unsigned aQH = smbase + rQ * 144 + ((lane >> 4) & 1) * 16;
    const unsigned aQL = aQH + 18432;
    const int rK = (lane & 7) + ((lane >> 4) & 1) * 8;
    const unsigned kOff = rK * 144 + ((lane >> 3) & 1) * 16;
    const int rV = (lane & 7) + ((lane >> 3) & 1) * 8;
    const unsigned vOff = 9216 + rV * 144 + ((lane >> 4) & 1) * 16;

    float m0 = -1e30f, m1 = -1e30f, l0 = 0.f, l1 = 0.f;
    float o[8][4];
    #pragma unroll
    for (int nt = 0; nt < 8; nt++)
        #pragma unroll
        for (int f = 0; f < 4; f++) o[nt][f] = 0.f;

    const int row0 = q0 + w * 16 + g, row1 = row0 + 8;

    for (int kt = 0; kt < nkt; kt++) {
        const int st = kt % 3;
        cpwait1();                 // tile kt resident (Q done by iter 0: groups 0,1 drained)
        __syncthreads();
        if (kt + 2 < nkt) load_kv(kt + 2, (kt + 2) % 3);

        const unsigned sbkv = smbase + 36864 + st * 18432;
        const unsigned aKH = sbkv + kOff,  aKL = aKH + 4608;
        const unsigned aVH = sbkv + vOff,  aVL = aVH + 4608;

        // ---- S = Q K^T (3-term), 32 kv cols ----
        float s[4][4];
        #pragma unroll
        for (int nt = 0; nt < 4; nt++)
            #pragma unroll
            for (int f = 0; f < 4; f++) s[nt][f] = 0.f;

        #pragma unroll
        for (int ks = 0; ks < 4; ks++) {
            unsigned qh[4], ql[4];
            ldsm4(qh, aQH + ks * 32);
            ldsm4(ql, aQL + ks * 32);
            unsigned bh[4][2], bl[4][2];
            #pragma unroll
            for (int ntp = 0; ntp < 2; ntp++) {
                unsigned off = (ntp * 16 * 72 + ks * 16) * 2;
                unsigned t[4];
                ldsm4(t, aKH + off);
                bh[2 * ntp][0] = t[0]; bh[2 * ntp][1] = t[1];
                bh[2 * ntp + 1][0] = t[2]; bh[2 * ntp + 1][1] = t[3];
                ldsm4(t, aKL + off);
                bl[2 * ntp][0] = t[0]; bl[2 * ntp][1] = t[1];
                bl[2 * ntp + 1][0] = t[2]; bl[2 * ntp + 1][1] = t[3];
            }
            #pragma unroll
            for (int nt = 0; nt < 4; nt++) {
                mmabf(s[nt], qh, bh[nt]);
                mmabf(s[nt], qh, bl[nt]);
                mmabf(s[nt], ql, bh[nt]);
            }
        }

        if (kt >= 4 * qt) {   // diagonal band tiles only
            #pragma unroll
            for (int nt = 0; nt < 4; nt++) {
                int col = kt * 32 + nt * 8 + 2 * c;
                if (col     > row0) s[nt][0] = -1e30f;
                if (col + 1 > row0) s[nt][1] = -1e30f;
                if (col     > row1) s[nt][2] = -1e30f;
                if (col + 1 > row1) s[nt][3] = -1e30f;
            }
        }

        // ---- online softmax ----
        float mx0 = -1e30f, mx1 = -1e30f;
        #pragma unroll
        for (int nt = 0; nt < 4; nt++) {
            mx0 = fmaxf(mx0, fmaxf(s[nt][0], s[nt][1]));
            mx1 = fmaxf(mx1, fmaxf(s[nt][2], s[nt][3]));
        }
        mx0 = fmaxf(mx0, __shfl_xor_sync(0xffffffffu, mx0, 1));
        mx0 = fmaxf(mx0, __shfl_xor_sync(0xffffffffu, mx0, 2));
        mx1 = fmaxf(mx1, __shfl_xor_sync(0xffffffffu, mx1, 1));
        mx1 = fmaxf(mx1, __shfl_xor_sync(0xffffffffu, mx1, 2));
        float mn0 = fmaxf(m0, mx0), mn1 = fmaxf(m1, mx1);
        float a0 = __expf(m0 - mn0), a1 = __expf(m1 - mn1);
        float sum0 = 0.f, sum1 = 0.f;
        #pragma unroll
        for (int nt = 0; nt < 4; nt++) {
            s[nt][0] = __expf(s[nt][0] - mn0);
            s[nt][1] = __expf(s[nt][1] - mn0);
            s[nt][2] = __expf(s[nt][2] - mn1);
            s[nt][3] = __expf(s[nt][3] - mn1);
            sum0 += s[nt][0] + s[nt][1];
            sum1 += s[nt][2] + s[nt][3];
        }
        sum0 += __shfl_xor_sync(0xffffffffu, sum0, 1);
        sum0 += __shfl_xor_sync(0xffffffffu, sum0, 2);
        sum1 += __shfl_xor_sync(0xffffffffu, sum1, 1);
        sum1 += __shfl_xor_sync(0xffffffffu, sum1, 2);
        l0 = l0 * a0 + sum0;  m0 = mn0;
        l1 = l1 * a1 + sum1;  m1 = mn1;
        #pragma unroll
        for (int nt = 0; nt < 8; nt++) {
            o[nt][0] *= a0; o[nt][1] *= a0;
            o[nt][2] *= a1; o[nt][3] *= a1;
        }

        // ---- P in registers (hi + lo) ----
        unsigned ph[4][2], pl[4][2];
        #pragma unroll
        for (int nt = 0; nt < 4; nt++) {
            ph[nt][0] = pk2bf(s[nt][0], s[nt][1]);
            ph[nt][1] = pk2bf(s[nt][2], s[nt][3]);
            pl[nt][0] = pk2bf(bflo(s[nt][0]), bflo(s[nt][1]));
            pl[nt][1] = pk2bf(bflo(s[nt][2]), bflo(s[nt][3]));
        }

        // ---- O += P V (3-term), kdim 32 ----
        #pragma unroll
        for (int ks = 0; ks < 2; ks++) {
            unsigned pah[4] = { ph[2 * ks][0], ph[2 * ks][1], ph[2 * ks + 1][0], ph[2 * ks + 1][1] };
            unsigned pal[4] = { pl[2 * ks][0], pl[2 * ks][1], pl[2 * ks + 1][0], pl[2 * ks + 1][1] };
            unsigned bh[8][2], bl[8][2];
            #pragma unroll
            for (int ntp = 0; ntp < 4; ntp++) {
                unsigned off = (ks * 16 * 72 + ntp * 16) * 2;
                unsigned t[4];
                ldsm4t(t, aVH + off);
                bh[2 * ntp][0] = t[0]; bh[2 * ntp][1] = t[1];
                bh[2 * ntp + 1][0] = t[2]; bh[2 * ntp + 1][1] = t[3];
                ldsm4t(t, aVL + off);
                bl[2 * ntp][0] = t[0]; bl[2 * ntp][1] = t[1];
                bl[2 * ntp + 1][0] = t[2]; bl[2 * ntp + 1][1] = t[3];
            }
            #pragma unroll
            for (int nt = 0; nt < 8; nt++) {
                mmabf(o[nt], pah, bh[nt]);
                mmabf(o[nt], pah, bl[nt]);
                mmabf(o[nt], pal, bh[nt]);
            }
        }
    }

    // normalize + write yH/yL
    float i0 = 1.f / l0, i1 = 1.f / l1;
    #pragma unroll
    for (int nt = 0; nt < 8; nt++) {
        int col = h * D_ + nt * 8 + 2 * c;
        float y00 = o[nt][0] * i0, y01 = o[nt][1] * i0;
        float y10 = o[nt][2] * i1, y11 = o[nt][3] * i1;
        size_t o0 = (size_t)(b * T_ + row0) * C_ + col;
        size_t o1 = (size_t)(b * T_ + row1) * C_ + col;
        *(unsigned*)&g_yH[o0] = pk2bf(y00, y01);
        *(unsigned*)&g_yL[o0] = pk2bf(bflo(y00), bflo(y01));
        *(unsigned*)&g_yH[o1] = pk2bf(y10, y11);
        *(unsigned*)&g_yL[o1] = pk2bf(bflo(y10), bflo(y11));
    }
}

// ---------------------------------------------------------------------------
#define GSMEM_BYTES 75776

extern "C" void kernel_launch(void* const* d_in, const int* in_sizes, int n_in,
                              void* d_out, int out_size)
{
    const float* x      = (const float*)d_in[0];
    const float* W_attn = (const float*)d_in[1];
    const float* b_attn = (const float*)d_in[2];
    const float* bQ     = (const float*)d_in[3];
    const float* bK     = (const float*)d_in[4];
    const float* W_proj = (const float*)d_in[5];
    const float* b_proj = (const float*)d_in[6];
    float* out = (float*)d_out;

    __nv_bfloat16 *xH, *xL, *WaH, *WaL, *WpH, *WpL, *qkvH, *qkvL, *yH, *yL;
    cudaGetSymbolAddress((void**)&xH, g_xH);     cudaGetSymbolAddress((void**)&xL, g_xL);
    cudaGetSymbolAddress((void**)&WaH, g_WaH);   cudaGetSymbolAddress((void**)&WaL, g_WaL);
    cudaGetSymbolAddress((void**)&WpH, g_WpH);   cudaGetSymbolAddress((void**)&WpL, g_WpL);
    cudaGetSymbolAddress((void**)&qkvH, g_qkvH); cudaGetSymbolAddress((void**)&qkvL, g_qkvL);
    cudaGetSymbolAddress((void**)&yH, g_yH);     cudaGetSymbolAddress((void**)&yL, g_yL);

    cudaFuncSetAttribute(gemm_bf16<0>, cudaFuncAttributeMaxDynamicSharedMemorySize, GSMEM_BYTES);
    cudaFuncSetAttribute(gemm_bf16<1>, cudaFuncAttributeMaxDynamicSharedMemorySize, GSMEM_BYTES);
    cudaFuncSetAttribute(attn_bf16, cudaFuncAttributeMaxDynamicSharedMemorySize, ASMEM_BYTES);

    // prepass: split operands once
    {
        int n4x = BT_ * C_ / 4, n4a = C_ * C3_ / 4, n4p = C_ * C_ / 4;
        split_kernel<<<(n4x + 255) / 256, 256>>>(x, xH, xL, n4x);
        split_kernel<<<(n4a + 255) / 256, 256>>>(W_attn, WaH, WaL, n4a);
        split_kernel<<<(n4p + 255) / 256, 256>>>(W_proj, WpH, WpL, n4p);
    }

    // 1) qkv (bf16 hi/lo out)
    gemm_bf16<0><<<dim3(C3_ / 128, BT_ / 128), 256, GSMEM_BYTES>>>(
        xH, xL, WaH, WaL, b_attn, bQ, bK, nullptr, qkvH, qkvL, BT_, C3_, C_);

    // 2) flash attention (bf16 hi/lo out)
    attn_bf16<<<dim3(T_ / 128, NH_, B_), 256, ASMEM_BYTES>>>();

    // 3) proj (float out)
    gemm_bf16<1><<<dim3(C_ / 128, BT_ / 128), 256, GSMEM_BYTES>>>(
        yH, yL, WpH, WpL, b_proj, nullptr, nullptr, out, nullptr, nullptr, BT_, C_, C_);
}

// round 17
// speedup vs baseline: 1.6306x; 1.0232x over previous
#include <cuda_runtime.h>
#include <cuda_bf16.h>

#define B_  4
#define T_  2048
#define C_  1024
#define NH_ 16
#define D_  64
#define BT_ (B_ * T_)      // 8192
#define C3_ (3 * C_)       // 3072

// ---- persistent bf16 hi/lo operand storage (no allocation allowed) ----
__device__ __nv_bfloat16 g_xH[(size_t)BT_ * C_],  g_xL[(size_t)BT_ * C_];
__device__ __nv_bfloat16 g_WaH[(size_t)C_ * C3_], g_WaL[(size_t)C_ * C3_];
__device__ __nv_bfloat16 g_WpH[(size_t)C_ * C_],  g_WpL[(size_t)C_ * C_];
__device__ __nv_bfloat16 g_qkvH[(size_t)BT_ * C3_], g_qkvL[(size_t)BT_ * C3_];
__device__ __nv_bfloat16 g_yH[(size_t)BT_ * C_],  g_yL[(size_t)BT_ * C_];

// ---------------- bf16 helpers ----------------
__device__ __forceinline__ void split4bf(float4 v, uint2 &h, uint2 &l) {
    float e[4] = { v.x, v.y, v.z, v.w };
    unsigned hs[4], ls[4];
    #pragma unroll
    for (int i = 0; i < 4; i++) {
        __nv_bfloat16 bh = __float2bfloat16(e[i]);
        hs[i] = __bfloat16_as_ushort(bh);
        ls[i] = __bfloat16_as_ushort(__float2bfloat16(e[i] - __bfloat162float(bh)));
    }
    h.x = hs[0] | (hs[1] << 16);  h.y = hs[2] | (hs[3] << 16);
    l.x = ls[0] | (ls[1] << 16);  l.y = ls[2] | (ls[3] << 16);
}
__device__ __forceinline__ unsigned pk2bf(float a, float b) {
    return __bfloat16_as_ushort(__float2bfloat16(a)) |
           ((unsigned)__bfloat16_as_ushort(__float2bfloat16(b)) << 16);
}
__device__ __forceinline__ float bflo(float x) {
    return x - __bfloat162float(__float2bfloat16(x));
}
__device__ __forceinline__ void mmabf(float c[4], const unsigned a[4], const unsigned b[2]) {
    asm("mma.sync.aligned.m16n8k16.row.col.f32.bf16.bf16.f32 "
        "{%0,%1,%2,%3}, {%4,%5,%6,%7}, {%8,%9}, {%0,%1,%2,%3};"
        : "+f"(c[0]), "+f"(c[1]), "+f"(c[2]), "+f"(c[3])
        : "r"(a[0]), "r"(a[1]), "r"(a[2]), "r"(a[3]), "r"(b[0]), "r"(b[1]));
}
__device__ __forceinline__ void ldsm4(unsigned r[4], unsigned a) {
    asm volatile("ldmatrix.sync.aligned.m8n8.x4.shared.b16 {%0,%1,%2,%3}, [%4];"
        : "=r"(r[0]), "=r"(r[1]), "=r"(r[2]), "=r"(r[3]) : "r"(a));
}
__device__ __forceinline__ void ldsm4t(unsigned r[4], unsigned a) {
    asm volatile("ldmatrix.sync.aligned.m8n8.x4.trans.shared.b16 {%0,%1,%2,%3}, [%4];"
        : "=r"(r[0]), "=r"(r[1]), "=r"(r[2]), "=r"(r[3]) : "r"(a));
}
__device__ __forceinline__ unsigned sptr(const void* p) {
    return (unsigned)__cvta_generic_to_shared(p);
}
__device__ __forceinline__ void cp16(unsigned s, const void* g) {
    asm volatile("cp.async.ca.shared.global [%0], [%1], 16;" :: "r"(s), "l"(g));
}
__device__ __forceinline__ void cpcommit() { asm volatile("cp.async.commit_group;"); }
__device__ __forceinline__ void cpwait0()  { asm volatile("cp.async.wait_group 0;" ::: "memory"); }
__device__ __forceinline__ void cpwait1()  { asm volatile("cp.async.wait_group 1;" ::: "memory"); }

// ---------------------------------------------------------------------------
// Prepass: split float -> bf16 hi/lo
// ---------------------------------------------------------------------------
__global__ void split_kernel(const float* __restrict__ src,
                             __nv_bfloat16* __restrict__ h,
                             __nv_bfloat16* __restrict__ l, int n4)
{
    int i = blockIdx.x * blockDim.x + threadIdx.x;
    if (i < n4) {
        float4 v = ((const float4*)src)[i];
        uint2 hh, ll; split4bf(v, hh, ll);
        ((uint2*)h)[i] = hh; ((uint2*)l)[i] = ll;
    }
}

// ---------------------------------------------------------------------------
// bf16x3 GEMM — R8 structure; mma terms reordered term-major (RAW spacing 1->4).
// ---------------------------------------------------------------------------
template<int MODE>
__global__ __launch_bounds__(256) void gemm_bf16(
    const __nv_bfloat16* __restrict__ AHg, const __nv_bfloat16* __restrict__ ALg,
    const __nv_bfloat16* __restrict__ WHg, const __nv_bfloat16* __restrict__ WLg,
    const float* __restrict__ bias, const float* __restrict__ bQ,
    const float* __restrict__ bK, float* __restrict__ CoutF,
    __nv_bfloat16* __restrict__ CoutH, __nv_bfloat16* __restrict__ CoutL,
    int M, int N, int K)
{
    extern __shared__ __align__(16) unsigned short smg[];

    const int tid = threadIdx.x, lane = tid & 31, warp = tid >> 5;
    const int g = lane >> 2, c = lane & 3;
    const int wm = warp >> 2, wn = warp & 3;
    const int crow = blockIdx.y * 128, ccol = blockIdx.x * 128;

    float acc[4][4][4];
    #pragma unroll
    for (int i = 0; i < 4; i++)
        #pragma unroll
        for (int j = 0; j < 4; j++)
            #pragma unroll
            for (int f = 0; f < 4; f++) acc[i][j][f] = 0.f;

    int ar[2], ac[2], br[2], bc[2];
    #pragma unroll
    for (int q = 0; q < 2; q++) {
        int cid = tid + 256 * q;
        ar[q] = cid >> 2;  ac[q] = (cid & 3) * 8;
        br[q] = cid >> 4;  bc[q] = (cid & 15) * 8;
    }
    const unsigned smbase = sptr(smg);

    const int rowA = wm * 64 + (lane & 7) + ((lane >> 3) & 1) * 8;
    const unsigned aAHb = smbase + (rowA * 40 + ((lane >> 4) & 1) * 8) * 2;
    const int rowB = (lane & 7) + ((lane >> 3) & 1) * 8;
    const int colB = wn * 32 + ((lane >> 4) & 1) * 8;
    const unsigned aBHb = smbase + (20480 + rowB * 136 + colB) * 2;

    const int nk = K >> 5;

    auto load_tile = [&](int kt, int st) {
        #pragma unroll
        for (int q = 0; q < 2; q++) {
            unsigned sa = smbase + (st * 5120 + ar[q] * 40 + ac[q]) * 2;
            cp16(sa, &AHg[(size_t)(crow + ar[q]) * K + kt * 32 + ac[q]]);
            cp16(sa + 20480, &ALg[(size_t)(crow + ar[q]) * K + kt * 32 + ac[q]]);
            unsigned sb = smbase + (20480 + st * 4352 + br[q] * 136 + bc[q]) * 2;
            cp16(sb, &WHg[(size_t)(kt * 32 + br[q]) * N + ccol + bc[q]]);
            cp16(sb + 17408, &WLg[(size_t)(kt * 32 + br[q]) * N + ccol + bc[q]]);
        }
        cpcommit();
    };

    load_tile(0, 0);

    for (int kt = 0; kt < nk; kt++) {
        const int st = kt & 1;
        cpwait0();
        __syncthreads();
        if (kt + 1 < nk) load_tile(kt + 1, st ^ 1);

        const unsigned aA = aAHb + st * 10240;
        const unsigned aB = aBHb + st * 8704;
        #pragma unroll
        for (int ks = 0; ks < 2; ks++) {
            unsigned bh[4][2], bl[4][2];
            #pragma unroll
            for (int ntp = 0; ntp < 2; ntp++) {
                unsigned off = (ks * 16 * 136 + ntp * 16) * 2;
                unsigned t[4];
                ldsm4t(t, aB + off);
                bh[2 * ntp][0] = t[0]; bh[2 * ntp][1] = t[1];
                bh[2 * ntp + 1][0] = t[2]; bh[2 * ntp + 1][1] = t[3];
                ldsm4t(t, aB + 17408 + off);
                bl[2 * ntp][0] = t[0]; bl[2 * ntp][1] = t[1];
                bl[2 * ntp + 1][0] = t[2]; bl[2 * ntp + 1][1] = t[3];
            }
            #pragma unroll
            for (int mt = 0; mt < 4; mt++) {
                unsigned off = (mt * 16 * 40 + ks * 16) * 2;
                unsigned ah[4], al[4];
                ldsm4(ah, aA + off);
                ldsm4(al, aA + 20480 + off);
                // term-major: same-accumulator RAW spacing 4 instead of 1
                #pragma unroll
                for (int nt = 0; nt < 4; nt++) mmabf(acc[mt][nt], ah, bh[nt]);
                #pragma unroll
                for (int nt = 0; nt < 4; nt++) mmabf(acc[mt][nt], ah, bl[nt]);
                #pragma unroll
                for (int nt = 0; nt < 4; nt++) mmabf(acc[mt][nt], al, bh[nt]);
            }
        }
        __syncthreads();
    }

    #pragma unroll
    for (int mt = 0; mt < 4; mt++)
    #pragma unroll
    for (int hh = 0; hh < 2; hh++) {
        int row = crow + wm * 64 + mt * 16 + g + 8 * hh;
        #pragma unroll
        for (int nt = 0; nt < 4; nt++) {
            int n0 = ccol + wn * 32 + nt * 8 + 2 * c;
            float v0 = acc[mt][nt][2 * hh]     + bias[n0];
            float v1 = acc[mt][nt][2 * hh + 1] + bias[n0 + 1];
            if (MODE == 0) {
                if (n0 < C_)          { v0 = (v0 + bQ[n0]) * 0.125f; v1 = (v1 + bQ[n0 + 1]) * 0.125f; }
                else if (n0 < 2 * C_) { v0 += bK[n0 - C_];           v1 += bK[n0 + 1 - C_]; }
                size_t o = (size_t)row * N + n0;
                *(unsigned*)&CoutH[o] = pk2bf(v0, v1);
                *(unsigned*)&CoutL[o] = pk2bf(bflo(v0), bflo(v1));
            } else {
                *(float2*)&CoutF[(size_t)row * N + n0] = make_float2(v0, v1);
            }
        }
    }
}

// ---------------------------------------------------------------------------
// Flash attention — R8 geometry (Bk=64, 3-stage ring, 147456 B, 1 CTA/SM);
// mma terms reordered term-major (RAW spacing 1->8).
// ---------------------------------------------------------------------------
#define ASMEM_BYTES 147456

__global__ __launch_bounds__(256) void attn_bf16()
{
    extern __shared__ __align__(16) unsigned short smn[];
    const unsigned smbase = sptr(smn);

    const int tid = threadIdx.x, lane = tid & 31, w = tid >> 5;
    const int g = lane >> 2, c = lane & 3;
    const int qt = blockIdx.x, h = blockIdx.y, b = blockIdx.z;
    const int q0 = qt * 128;
    const size_t rb = (size_t)b * T_ * C3_ + (size_t)h * D_;

    const int nkt = 2 * qt + 2;

    auto load_kv = [&](int kt, int st) {
        #pragma unroll
        for (int q = 0; q < 2; q++) {
            int idx = tid + 256 * q;
            int kc = idx >> 3, d0 = (idx & 7) * 8;
            size_t go = rb + (size_t)(kt * 64 + kc) * C3_ + d0;
            unsigned sb = smbase + (18432 + kc * 72 + d0) * 2 + st * 36864;
            cp16(sb,          &g_qkvH[go + C_]);
            cp16(sb + 9216,   &g_qkvL[go + C_]);
            cp16(sb + 18432,  &g_qkvH[go + 2 * C_]);
            cp16(sb + 27648,  &g_qkvL[go + 2 * C_]);
        }
        cpcommit();
    };

    // Prologue: Q + KV0 (group 0), KV1 (group 1)
    #pragma unroll
    for (int r = 0; r < 4; r++) {
        int idx = tid + 256 * r;
        int qq = idx >> 3, d0 = (idx & 7) * 8;
        size_t gi = rb + (size_t)(q0 + qq) * C3_ + d0;
        unsigned sb = smbase + (qq * 72 + d0) * 2;
        cp16(sb, &g_qkvH[gi]);
        cp16(sb + 18432, &g_qkvL[gi]);
    }
    load_kv(0, 0);      // commits group 0 (Q + KV0)
    load_kv(1, 1);      // group 1

    const int rQ = w * 16 + (lane & 7) + ((lane >> 3) & 1) * 8;
    const unsigned aQH = smbase + (rQ * 72 + ((lane >> 4) & 1) * 8) * 2;
    const unsigned aQL = aQH + 18432;
    const int rK = (lane & 7) + ((lane >> 4) & 1) * 8;
    const unsigned kOff = (18432 + rK * 72 + ((lane >> 3) & 1) * 8) * 2;
    const int rV = (lane & 7) + ((lane >> 3) & 1) * 8;
    const unsigned vOff = (18432 + 9216 + rV * 72 + ((lane >> 4) & 1) * 8) * 2;

    float m0 = -1e30f, m1 = -1e30f, l0 = 0.f, l1 = 0.f;
    float o[8][4];
    #pragma unroll
    for (int nt = 0; nt < 8; nt++)
        #pragma unroll
        for (int f = 0; f < 4; f++) o[nt][f] = 0.f;

    const int row0 = q0 + w * 16 + g, row1 = row0 + 8;

    for (int kt = 0; kt < nkt; kt++) {
        const int st = kt % 3;
        cpwait1();
        __syncthreads();
        if (kt + 2 < nkt) load_kv(kt + 2, (kt + 2) % 3);

        const unsigned aKH = smbase + kOff + st * 36864;
        const unsigned aKL = aKH + 9216;
        const unsigned aVH = smbase + vOff + st * 36864;
        const unsigned aVL = aVH + 9216;

        // ---- S = Q K^T (3-term, term-major) ----
        float s[8][4];
        #pragma unroll
        for (int nt = 0; nt < 8; nt++)
            #pragma unroll
            for (int f = 0; f < 4; f++) s[nt][f] = 0.f;

        #pragma unroll
        for (int ks = 0; ks < 4; ks++) {
            unsigned qh[4], ql[4];
            ldsm4(qh, aQH + ks * 32);
            ldsm4(ql, aQL + ks * 32);
            unsigned bh[8][2], bl[8][2];
            #pragma unroll
            for (int ntp = 0; ntp < 4; ntp++) {
                unsigned off = (ntp * 16 * 72 + ks * 16) * 2;
                unsigned t[4];
                ldsm4(t, aKH + off);
                bh[2 * ntp][0] = t[0]; bh[2 * ntp][1] = t[1];
                bh[2 * ntp + 1][0] = t[2]; bh[2 * ntp + 1][1] = t[3];
                ldsm4(t, aKL + off);
                bl[2 * ntp][0] = t[0]; bl[2 * ntp][1] = t[1];
                bl[2 * ntp + 1][0] = t[2]; bl[2 * ntp + 1][1] = t[3];
            }
            #pragma unroll
            for (int nt = 0; nt < 8; nt++) mmabf(s[nt], qh, bh[nt]);
            #pragma unroll
            for (int nt = 0; nt < 8; nt++) mmabf(s[nt], qh, bl[nt]);
            #pragma unroll
            for (int nt = 0; nt < 8; nt++) mmabf(s[nt], ql, bh[nt]);
        }

        if (kt >= 2 * qt) {
            #pragma unroll
            for (int nt = 0; nt < 8; nt++) {
                int col = kt * 64 + nt * 8 + 2 * c;
                if (col     > row0) s[nt][0] = -1e30f;
                if (col + 1 > row0) s[nt][1] = -1e30f;
                if (col     > row1) s[nt][2] = -1e30f;
                if (col + 1 > row1) s[nt][3] = -1e30f;
            }
        }

        // ---- online softmax ----
        float mx0 = -1e30f, mx1 = -1e30f;
        #pragma unroll
        for (int nt = 0; nt < 8; nt++) {
            mx0 = fmaxf(mx0, fmaxf(s[nt][0], s[nt][1]));
            mx1 = fmaxf(mx1, fmaxf(s[nt][2], s[nt][3]));
        }
        mx0 = fmaxf(mx0, __shfl_xor_sync(0xffffffffu, mx0, 1));
        mx0 = fmaxf(mx0, __shfl_xor_sync(0xffffffffu, mx0, 2));
        mx1 = fmaxf(mx1, __shfl_xor_sync(0xffffffffu, mx1, 1));
        mx1 = fmaxf(mx1, __shfl_xor_sync(0xffffffffu, mx1, 2));
        float mn0 = fmaxf(m0, mx0), mn1 = fmaxf(m1, mx1);
        float a0 = __expf(m0 - mn0), a1 = __expf(m1 - mn1);
        float sum0 = 0.f, sum1 = 0.f;
        #pragma unroll
        for (int nt = 0; nt < 8; nt++) {
            s[nt][0] = __expf(s[nt][0] - mn0);
            s[nt][1] = __expf(s[nt][1] - mn0);
            s[nt][2] = __expf(s[nt][2] - mn1);
            s[nt][3] = __expf(s[nt][3] - mn1);
            sum0 += s[nt][0] + s[nt][1];
            sum1 += s[nt][2] + s[nt][3];
        }
        sum0 += __shfl_xor_sync(0xffffffffu, sum0, 1);
        sum0 += __shfl_xor_sync(0xffffffffu, sum0, 2);
        sum1 += __shfl_xor_sync(0xffffffffu, sum1, 1);
        sum1 += __shfl_xor_sync(0xffffffffu, sum1, 2);
        l0 = l0 * a0 + sum0;  m0 = mn0;
        l1 = l1 * a1 + sum1;  m1 = mn1;
        #pragma unroll
        for (int nt = 0; nt < 8; nt++) {
            o[nt][0] *= a0; o[nt][1] *= a0;
            o[nt][2] *= a1; o[nt][3] *= a1;
        }

        // ---- P in registers (hi + lo) ----
        unsigned ph[8][2], pl[8][2];
        #pragma unroll
        for (int nt = 0; nt < 8; nt++) {
            ph[nt][0] = pk2bf(s[nt][0], s[nt][1]);
            ph[nt][1] = pk2bf(s[nt][2], s[nt][3]);
            pl[nt][0] = pk2bf(bflo(s[nt][0]), bflo(s[nt][1]));
            pl[nt][1] = pk2bf(bflo(s[nt][2]), bflo(s[nt][3]));
        }

        // ---- O += P V (3-term, term-major) ----
        #pragma unroll
        for (int ks = 0; ks < 4; ks++) {
            unsigned pah[4] = { ph[2 * ks][0], ph[2 * ks][1], ph[2 * ks + 1][0], ph[2 * ks + 1][1] };
            unsigned pal[4] = { pl[2 * ks][0], pl[2 * ks][1], pl[2 * ks + 1][0], pl[2 * ks + 1][1] };
            unsigned bh[8][2], bl[8][2];
            #pragma unroll
            for (int ntp = 0; ntp < 4; ntp++) {
                unsigned off = (ks * 16 * 72 + ntp * 16) * 2;
                unsigned t[4];
                ldsm4t(t, aVH + off);
                bh[2 * ntp][0] = t[0]; bh[2 * ntp][1] = t[1];
                bh[2 * ntp + 1][0] = t[2]; bh[2 * ntp + 1][1] = t[3];
                ldsm4t(t, aVL + off);
                bl[2 * ntp][0] = t[0]; bl[2 * ntp][1] = t[1];
                bl[2 * ntp + 1][0] = t[2]; bl[2 * ntp + 1][1] = t[3];
            }
            #pragma unroll
            for (int nt = 0; nt < 8; nt++) mmabf(o[nt], pah, bh[nt]);
            #pragma unroll
            for (int nt = 0; nt < 8; nt++) mmabf(o[nt], pah, bl[nt]);
            #pragma unroll
            for (int nt = 0; nt < 8; nt++) mmabf(o[nt], pal, bh[nt]);
        }
    }

    // normalize + write yH/yL
    float i0 = 1.f / l0, i1 = 1.f / l1;
    #pragma unroll
    for (int nt = 0; nt < 8; nt++) {
        int col = h * D_ + nt * 8 + 2 * c;
        float y00 = o[nt][0] * i0, y01 = o[nt][1] * i0;
        float y10 = o[nt][2] * i1, y11 = o[nt][3] * i1;
        size_t o0 = (size_t)(b * T_ + row0) * C_ + col;
        size_t o1 = (size_t)(b * T_ + row1) * C_ + col;
        *(unsigned*)&g_yH[o0] = pk2bf(y00, y01);
        *(unsigned*)&g_yL[o0] = pk2bf(bflo(y00), bflo(y01));
        *(unsigned*)&g_yH[o1] = pk2bf(y10, y11);
        *(unsigned*)&g_yL[o1] = pk2bf(bflo(y10), bflo(y11));
    }
}

// ---------------------------------------------------------------------------
#define GSMEM_BYTES 75776

extern "C" void kernel_launch(void* const* d_in, const int* in_sizes, int n_in,
                              void* d_out, int out_size)
{
    const float* x      = (const float*)d_in[0];
    const float* W_attn = (const float*)d_in[1];
    const float* b_attn = (const float*)d_in[2];
    const float* bQ     = (const float*)d_in[3];
    const float* bK     = (const float*)d_in[4];
    const float* W_proj = (const float*)d_in[5];
    const float* b_proj = (const float*)d_in[6];
    float* out = (float*)d_out;

    __nv_bfloat16 *xH, *xL, *WaH, *WaL, *WpH, *WpL, *qkvH, *qkvL, *yH, *yL;
    cudaGetSymbolAddress((void**)&xH, g_xH);     cudaGetSymbolAddress((void**)&xL, g_xL);
    cudaGetSymbolAddress((void**)&WaH, g_WaH);   cudaGetSymbolAddress((void**)&WaL, g_WaL);
    cudaGetSymbolAddress((void**)&WpH, g_WpH);   cudaGetSymbolAddress((void**)&WpL, g_WpL);
    cudaGetSymbolAddress((void**)&qkvH, g_qkvH); cudaGetSymbolAddress((void**)&qkvL, g_qkvL);
    cudaGetSymbolAddress((void**)&yH, g_yH);     cudaGetSymbolAddress((void**)&yL, g_yL);

    cudaFuncSetAttribute(gemm_bf16<0>, cudaFuncAttributeMaxDynamicSharedMemorySize, GSMEM_BYTES);
    cudaFuncSetAttribute(gemm_bf16<1>, cudaFuncAttributeMaxDynamicSharedMemorySize, GSMEM_BYTES);
    cudaFuncSetAttribute(attn_bf16, cudaFuncAttributeMaxDynamicSharedMemorySize, ASMEM_BYTES);

    // prepass: split operands once
    {
        int n4x = BT_ * C_ / 4, n4a = C_ * C3_ / 4, n4p = C_ * C_ / 4;
        split_kernel<<<(n4x + 255) / 256, 256>>>(x, xH, xL, n4x);
        split_kernel<<<(n4a + 255) / 256, 256>>>(W_attn, WaH, WaL, n4a);
        split_kernel<<<(n4p + 255) / 256, 256>>>(W_proj, WpH, WpL, n4p);
    }

    // 1) qkv (bf16 hi/lo out)
    gemm_bf16<0><<<dim3(C3_ / 128, BT_ / 128), 256, GSMEM_BYTES>>>(
        xH, xL, WaH, WaL, b_attn, bQ, bK, nullptr, qkvH, qkvL, BT_, C3_, C_);

    // 2) flash attention (bf16 hi/lo out)
    attn_bf16<<<dim3(T_ / 128, NH_, B_), 256, ASMEM_BYTES>>>();

    // 3) proj (float out)
    gemm_bf16<1><<<dim3(C_ / 128, BT_ / 128), 256, GSMEM_BYTES>>>(
        yH, yL, WpH, WpL, b_proj, nullptr, nullptr, out, nullptr, nullptr, BT_, C_, C_);
}